// round 1
// baseline (speedup 1.0000x reference)
#include <cuda_runtime.h>
#include <cstdint>

// Problem constants (fixed shapes from the reference)
#define N_NODES 4096
#define E_EDGES 262144
#define IN_DIM  256
#define NBOND   5
#define NATOM   16
#define LATENT  128

// Output layout in d_out (float32), tuple order (latent, atoms, bonds):
//   latent_pred : [0, 524288)
//   atoms_pred  : [524288, 589824)
//   bonds_pred  : [589824, 1900544)
#define OFF_LATENT 0
#define OFF_ATOMS  524288
#define OFF_BONDS  589824

// ---------------------------------------------------------------------------
// Scratch (static __device__ globals — no allocations allowed)
// ---------------------------------------------------------------------------
__device__ int   g_table[(size_t)N_NODES * N_NODES];   // 64 MB pair table
__device__ float g_s1[(size_t)N_NODES * IN_DIM];       // silu(s @ W_shared^T + b)
__device__ float g_esym[(size_t)E_EDGES * 16];         // symmetrized edge features
__device__ int   g_jj[E_EDGES];
__device__ int   g_ii[E_EDGES];
__device__ int   g_flag;                               // 1 if edge_index is int64

// ---------------------------------------------------------------------------
// Detect dtype of edge_index (int32 vs int64). For int64 little-endian data
// with values in [0,4096), every odd 32-bit word is 0.
// ---------------------------------------------------------------------------
__global__ void detect_kernel(const void* __restrict__ eidx) {
    if (blockIdx.x == 0 && threadIdx.x == 0) {
        const int* p = (const int*)eidx;
        int is64 = 1;
        #pragma unroll 1
        for (int k = 1; k < 129; k += 2) {
            if (p[k] != 0) { is64 = 0; break; }
        }
        g_flag = is64;
    }
}

__global__ void convert_kernel(const void* __restrict__ eidx) {
    int k = blockIdx.x * blockDim.x + threadIdx.x;
    if (k >= E_EDGES) return;
    int j, i;
    if (g_flag) {
        const long long* p = (const long long*)eidx;
        j = (int)p[k];
        i = (int)p[E_EDGES + k];
    } else {
        const int* p = (const int*)eidx;
        j = p[k];
        i = p[E_EDGES + k];
    }
    g_jj[k] = j;
    g_ii[k] = i;
}

// Clear exactly the table entries we will later read (fwd + reverse keys).
__global__ void clear_kernel() {
    int k = blockIdx.x * blockDim.x + threadIdx.x;
    if (k >= E_EDGES) return;
    int j = g_jj[k], i = g_ii[k];
    g_table[j * N_NODES + i] = -1;
    g_table[i * N_NODES + j] = -1;
}

// "Last write wins" scatter semantics via atomicMax on edge index.
__global__ void scatter_kernel() {
    int k = blockIdx.x * blockDim.x + threadIdx.x;
    if (k >= E_EDGES) return;
    atomicMax(&g_table[g_jj[k] * N_NODES + g_ii[k]], k);
}

// e_sym[k] = 0.5 * (e[fwd] + (rev >= 0 ? e[rev] : 0))
__global__ void esym_kernel(const float* __restrict__ e) {
    int k = blockIdx.x * blockDim.x + threadIdx.x;
    if (k >= E_EDGES) return;
    int j = g_jj[k], i = g_ii[k];
    int f = g_table[j * N_NODES + i];   // >= 0 (edge k itself wrote it)
    int r = g_table[i * N_NODES + j];
    const float4* ef = (const float4*)(e + (size_t)f * 16);
    float4*       o  = (float4*)(g_esym + (size_t)k * 16);
    if (r >= 0) {
        const float4* er = (const float4*)(e + (size_t)r * 16);
        #pragma unroll
        for (int c = 0; c < 4; c++) {
            float4 a = ef[c], b = er[c];
            o[c] = make_float4(0.5f * (a.x + b.x), 0.5f * (a.y + b.y),
                               0.5f * (a.z + b.z), 0.5f * (a.w + b.w));
        }
    } else {
        #pragma unroll
        for (int c = 0; c < 4; c++) {
            float4 a = ef[c];
            o[c] = make_float4(0.5f * a.x, 0.5f * a.y, 0.5f * a.z, 0.5f * a.w);
        }
    }
}

// ---------------------------------------------------------------------------
// Tiled SGEMM: C[m][t] = act( sum_k A[m][k] * W[t][k] + bias[t] )
// A row-major (M x 256), W row-major (T x 256). BM=BN=64, BK=16, 256 threads,
// 4x4 register tile per thread.
// SILU=1: apply silu, write g_s1 (T == 256).
// SPLIT=1: A read from g_s1; write atoms (t<16) / latent (t>=16) in d_out.
// ---------------------------------------------------------------------------
template <int SILU, int SPLIT>
__global__ void __launch_bounds__(256)
gemm_kernel(const float* __restrict__ A_in, const float* __restrict__ W,
            const float* __restrict__ bias, float* __restrict__ out, int T) {
    __shared__ float As[16][64];
    __shared__ float Ws[16][64];

    const float* A = SPLIT ? g_s1 : A_in;

    int tid = threadIdx.x;
    int tn = tid & 15;
    int tm = tid >> 4;
    int m0 = blockIdx.y * 64;
    int t0 = blockIdx.x * 64;

    int lr = tid >> 2;          // 0..63
    int lc = (tid & 3) * 4;     // k offset within 16

    float acc[4][4] = {};

    for (int k0 = 0; k0 < IN_DIM; k0 += 16) {
        float4 av = *(const float4*)(A + (size_t)(m0 + lr) * IN_DIM + k0 + lc);
        As[lc + 0][lr] = av.x; As[lc + 1][lr] = av.y;
        As[lc + 2][lr] = av.z; As[lc + 3][lr] = av.w;

        float4 wv = make_float4(0.f, 0.f, 0.f, 0.f);
        if (t0 + lr < T)
            wv = *(const float4*)(W + (size_t)(t0 + lr) * IN_DIM + k0 + lc);
        Ws[lc + 0][lr] = wv.x; Ws[lc + 1][lr] = wv.y;
        Ws[lc + 2][lr] = wv.z; Ws[lc + 3][lr] = wv.w;

        __syncthreads();

        #pragma unroll
        for (int kk = 0; kk < 16; kk++) {
            float4 a = *(const float4*)&As[kk][tm * 4];
            float4 w = *(const float4*)&Ws[kk][tn * 4];
            acc[0][0] += a.x * w.x; acc[0][1] += a.x * w.y; acc[0][2] += a.x * w.z; acc[0][3] += a.x * w.w;
            acc[1][0] += a.y * w.x; acc[1][1] += a.y * w.y; acc[1][2] += a.y * w.z; acc[1][3] += a.y * w.w;
            acc[2][0] += a.z * w.x; acc[2][1] += a.z * w.y; acc[2][2] += a.z * w.z; acc[2][3] += a.z * w.w;
            acc[3][0] += a.w * w.x; acc[3][1] += a.w * w.y; acc[3][2] += a.w * w.z; acc[3][3] += a.w * w.w;
        }
        __syncthreads();
    }

    #pragma unroll
    for (int u = 0; u < 4; u++) {
        int m = m0 + tm * 4 + u;
        #pragma unroll
        for (int v = 0; v < 4; v++) {
            int t = t0 + tn * 4 + v;
            if (t < T) {
                float x = acc[u][v] + bias[t];
                if (SILU) x = x * __fdividef(1.f, 1.f + __expf(-x));
                if (!SPLIT) {
                    g_s1[(size_t)m * 256 + t] = x;
                } else {
                    if (t < NATOM)
                        out[OFF_ATOMS + (size_t)m * NATOM + t] = x;
                    else
                        out[OFF_LATENT + (size_t)m * LATENT + (t - NATOM)] = x;
                }
            }
        }
    }
}

// ---------------------------------------------------------------------------
// Edge head. Block = 256 threads, thread t = output dim t.
// W_bond row (16) + W_bonds column (5) live in registers; e_sym broadcast
// from smem; s1 gathers coalesced (L2-resident). 5-way per-edge reduction:
// warp shuffle -> smem partials -> 80-thread finalize, 16 edges per sync.
// ---------------------------------------------------------------------------
#define EB 16
#define EDGES_PER_BLOCK 128

__global__ void __launch_bounds__(256)
edge_kernel(float* __restrict__ out_bonds,
            const float* __restrict__ W_bond, const float* __restrict__ b_bond,
            const float* __restrict__ W_bonds, const float* __restrict__ b_bonds) {
    int t = threadIdx.x;
    int warp = t >> 5, lane = t & 31;

    float wb[16];
    #pragma unroll
    for (int c = 0; c < 16; c++) wb[c] = W_bond[t * 16 + c];
    float bb = b_bond[t];
    float wq[NBOND];
    #pragma unroll
    for (int q = 0; q < NBOND; q++) wq[q] = W_bonds[q * IN_DIM + t];

    __shared__ float es[EB][16];
    __shared__ int   sj[EB], si[EB];
    __shared__ float red[EB][8][NBOND];

    int base0 = blockIdx.x * EDGES_PER_BLOCK;

    for (int bb0 = 0; bb0 < EDGES_PER_BLOCK; bb0 += EB) {
        int base = base0 + bb0;

        if (t < EB) { sj[t] = g_jj[base + t]; si[t] = g_ii[base + t]; }
        es[t >> 4][t & 15] = g_esym[(size_t)base * 16 + t];
        __syncthreads();

        // one-edge lookahead prefetch for s1 gathers
        float pj = g_s1[sj[0] * IN_DIM + t];
        float pi = g_s1[si[0] * IN_DIM + t];

        #pragma unroll
        for (int b = 0; b < EB; b++) {
            float svj = pj, svi = pi;
            if (b + 1 < EB) {
                pj = g_s1[sj[b + 1] * IN_DIM + t];
                pi = g_s1[si[b + 1] * IN_DIM + t];
            }
            float acc = bb;
            #pragma unroll
            for (int c = 0; c < 16; c++) acc += es[b][c] * wb[c];
            acc += svj + svi;
            float f = acc * __fdividef(1.f, 1.f + __expf(-acc));

            float p0 = f * wq[0], p1 = f * wq[1], p2 = f * wq[2],
                  p3 = f * wq[3], p4 = f * wq[4];
            #pragma unroll
            for (int off = 16; off > 0; off >>= 1) {
                p0 += __shfl_xor_sync(0xffffffffu, p0, off);
                p1 += __shfl_xor_sync(0xffffffffu, p1, off);
                p2 += __shfl_xor_sync(0xffffffffu, p2, off);
                p3 += __shfl_xor_sync(0xffffffffu, p3, off);
                p4 += __shfl_xor_sync(0xffffffffu, p4, off);
            }
            if (lane == 0) {
                red[b][warp][0] = p0; red[b][warp][1] = p1; red[b][warp][2] = p2;
                red[b][warp][3] = p3; red[b][warp][4] = p4;
            }
        }
        __syncthreads();

        if (t < EB * NBOND) {
            int b = t / NBOND, q = t - b * NBOND;
            float s = b_bonds[q];
            #pragma unroll
            for (int w = 0; w < 8; w++) s += red[b][w][q];
            out_bonds[(size_t)(base + b) * NBOND + q] = s;
        }
        __syncthreads();
    }
}

// ---------------------------------------------------------------------------
// Launch
// ---------------------------------------------------------------------------
extern "C" void kernel_launch(void* const* d_in, const int* in_sizes, int n_in,
                              void* d_out, int out_size) {
    const float* s        = (const float*)d_in[0];
    const float* e        = (const float*)d_in[1];
    // d_in[2] = batch (unused)
    const void*  eidx     = d_in[3];
    const float* W_shared = (const float*)d_in[4];
    const float* b_shared = (const float*)d_in[5];
    const float* W_bond   = (const float*)d_in[6];
    const float* b_bond   = (const float*)d_in[7];
    const float* W_bonds  = (const float*)d_in[8];
    const float* b_bonds  = (const float*)d_in[9];
    const float* W_atoms  = (const float*)d_in[10];
    const float* b_atoms  = (const float*)d_in[11];
    float* out = (float*)d_out;

    const int tpb = 256;
    const int eblocks = E_EDGES / tpb;   // 1024

    detect_kernel<<<1, 32>>>(eidx);
    convert_kernel<<<eblocks, tpb>>>(eidx);
    clear_kernel<<<eblocks, tpb>>>();
    scatter_kernel<<<eblocks, tpb>>>();
    esym_kernel<<<eblocks, tpb>>>(e);

    // s1 = silu(s @ W_shared^T + b_shared) -> g_s1
    gemm_kernel<1, 0><<<dim3(4, 64), 256>>>(s, W_shared, b_shared, out, 256);
    // atoms_out = s1 @ W_atoms^T + b_atoms -> latent/atoms regions of d_out
    gemm_kernel<0, 1><<<dim3(3, 64), 256>>>(nullptr, W_atoms, b_atoms, out, 144);

    edge_kernel<<<E_EDGES / EDGES_PER_BLOCK, 256>>>(out + OFF_BONDS,
                                                    W_bond, b_bond, W_bonds, b_bonds);
}